// round 14
// baseline (speedup 1.0000x reference)
#include <cuda_runtime.h>
#include <math.h>

#define MAX_NODES 20000
#define MAX_EDGES 640000
#define SLOTS     160          // padded per-node edge capacity (max degree ~66)
#define TABN      8192
#define DMAX      2.0f
#define TSCALE    4095.5f      // (TABN-1)/DMAX

// Static scratch (no allocation allowed).
__device__ float  g_table[TABN * 32];              // rad = F(d) lookup, 1MB (L2-hot)
__device__ int    g_count[MAX_NODES];
__device__ float4 g_slot_rs[MAX_NODES * SLOTS];    // per-slot payload (X,Y,Z,u)

// ---------------------------------------------------------------------------
// Packed f32x2 helpers (Blackwell — only reachable via PTX)
// ---------------------------------------------------------------------------
typedef unsigned long long u64;

__device__ __forceinline__ u64 pack2(float lo, float hi) {
    u64 r;
    asm("mov.b64 %0, {%1, %2};" : "=l"(r) : "f"(lo), "f"(hi));
    return r;
}
__device__ __forceinline__ void unpack2(u64 v, float& lo, float& hi) {
    asm("mov.b64 {%0, %1}, %2;" : "=f"(lo), "=f"(hi) : "l"(v));
}
#define FMA2(d, a, b, c) \
    asm("fma.rn.f32x2 %0, %1, %2, %3;" : "=l"(d) : "l"(a), "l"(b), "l"(c))
#define MUL2(d, a, b) \
    asm("mul.rn.f32x2 %0, %1, %2;" : "=l"(d) : "l"(a), "l"(b))
#define ADD2(d, a, b) \
    asm("add.rn.f32x2 %0, %1, %2;" : "=l"(d) : "l"(a), "l"(b))

// ---------------------------------------------------------------------------
// Per-edge prep: compute (X,Y,Z,u) and write it DIRECTLY into the node's
// slot list. u pre-clamped so the node kernel needs no idx clamp.
// ---------------------------------------------------------------------------
__global__ void prep_kernel(const float* __restrict__ r_ij,
                            const int* __restrict__ edges_src, int E) {
    int e = blockIdx.x * blockDim.x + threadIdx.x;
    if (e >= E) return;

    int n = edges_src[e];
    int slot = atomicAdd(&g_count[n], 1);

    float rx = r_ij[3 * e + 0];
    float ry = r_ij[3 * e + 1];
    float rz = r_ij[3 * e + 2];
    float d2 = rx * rx + ry * ry + rz * rz;
    float d  = sqrtf(d2);
    // rs = tens_sigmoid(r * 7): r*7 / sqrt(1 + 49*d2)
    float inv = rsqrtf(1.0f + 49.0f * d2) * 7.0f;
    float u = fminf(d * TSCALE, (float)(TABN - 1) - 0.5f);  // idx always <= TABN-2
    if (slot < SLOTS)
        g_slot_rs[n * SLOTS + slot] = make_float4(rx * inv, ry * inv, rz * inv, u);
}

// ---------------------------------------------------------------------------
// Table builder (also zeroes g_count — fused to save a launch).
// rad = F(d) for TABN samples of d in [0, DMAX], packed-f32x2 MLP.
// ---------------------------------------------------------------------------
__global__ __launch_bounds__(128)
void table_kernel(const float* __restrict__ w_rad,  const float* __restrict__ b_rad,
                  const float* __restrict__ w_direct,
                  const float* __restrict__ w1, const float* __restrict__ b1,
                  const float* __restrict__ w2, const float* __restrict__ b2,
                  const float* __restrict__ w3, const float* __restrict__ b3,
                  int N)
{
    __shared__ __align__(16) float s_wrad[8 * 32];
    __shared__ __align__(16) float s_brad[32];
    __shared__ __align__(16) float s_wdir[32 * 32];
    __shared__ __align__(16) float s_w1[32 * 64];
    __shared__ __align__(16) float s_b1[64];
    __shared__ __align__(16) float s_w2[64 * 64];
    __shared__ __align__(16) float s_b2[64];
    __shared__ __align__(16) float s_w3[64 * 32];
    __shared__ __align__(16) float s_b3[32];

    int t = blockIdx.x * blockDim.x + threadIdx.x;
    if (t < N) g_count[t] = 0;          // fused zeroing
    if (blockIdx.x * blockDim.x >= TABN) return;   // zero-only blocks

    for (int i = threadIdx.x; i < 8 * 32;  i += blockDim.x) s_wrad[i] = w_rad[i];
    for (int i = threadIdx.x; i < 32;      i += blockDim.x) s_brad[i] = b_rad[i];
    for (int i = threadIdx.x; i < 32 * 32; i += blockDim.x) s_wdir[i] = w_direct[i];
    for (int i = threadIdx.x; i < 32 * 64; i += blockDim.x) s_w1[i]   = w1[i];
    for (int i = threadIdx.x; i < 64;      i += blockDim.x) s_b1[i]   = b1[i];
    for (int i = threadIdx.x; i < 64 * 64; i += blockDim.x) s_w2[i]   = w2[i];
    for (int i = threadIdx.x; i < 64;      i += blockDim.x) s_b2[i]   = b2[i];
    for (int i = threadIdx.x; i < 64 * 32; i += blockDim.x) s_w3[i]   = w3[i];
    for (int i = threadIdx.x; i < 32;      i += blockDim.x) s_b3[i]   = b3[i];
    __syncthreads();

    if (t >= TABN) return;

    float d = (float)t * (DMAX / (float)(TABN - 1));

    // 8 Gaussian RBFs; centers k/7, width 1/8
    float enc[8];
    #pragma unroll
    for (int k = 0; k < 8; k++) {
        float x = (d - (float)k * (1.0f / 7.0f)) * 8.0f;
        enc[k] = __expf(-x * x);
    }

    const u64* W_RAD = (const u64*)s_wrad;
    const u64* B_RAD = (const u64*)s_brad;
    const u64* W_DIR = (const u64*)s_wdir;
    const u64* W_1   = (const u64*)s_w1;
    const u64* B_1   = (const u64*)s_b1;
    const u64* W_2   = (const u64*)s_w2;
    const u64* B_2   = (const u64*)s_b2;
    const u64* W_3   = (const u64*)s_w3;
    const u64* B_3   = (const u64*)s_b3;

    u64 h2[16];
    #pragma unroll
    for (int p = 0; p < 16; p++) h2[p] = B_RAD[p];
    #pragma unroll
    for (int k = 0; k < 8; k++) {
        u64 ek2 = pack2(enc[k], enc[k]);
        #pragma unroll
        for (int p = 0; p < 16; p++) FMA2(h2[p], ek2, W_RAD[k * 16 + p], h2[p]);
    }

    u64 rad2[16];
    #pragma unroll
    for (int p = 0; p < 16; p++) rad2[p] = 0;
    u64 t1[32];
    #pragma unroll
    for (int p = 0; p < 32; p++) t1[p] = B_1[p];

    #pragma unroll
    for (int kp = 0; kp < 16; kp++) {
        float hk0, hk1;
        unpack2(h2[kp], hk0, hk1);
        u64 a0 = pack2(hk0, hk0);
        u64 a1 = pack2(hk1, hk1);
        int k0 = 2 * kp, k1 = 2 * kp + 1;
        #pragma unroll
        for (int p = 0; p < 16; p++) {
            FMA2(rad2[p], a0, W_DIR[k0 * 16 + p], rad2[p]);
            FMA2(rad2[p], a1, W_DIR[k1 * 16 + p], rad2[p]);
        }
        #pragma unroll
        for (int p = 0; p < 32; p++) {
            FMA2(t1[p], a0, W_1[k0 * 32 + p], t1[p]);
            FMA2(t1[p], a1, W_1[k1 * 32 + p], t1[p]);
        }
    }
    #pragma unroll
    for (int p = 0; p < 32; p++) {
        float lo, hi;
        unpack2(t1[p], lo, hi);
        lo = fmaxf(lo, 0.1f * lo);
        hi = fmaxf(hi, 0.1f * hi);
        t1[p] = pack2(lo, hi);
    }

    u64 t2[32];
    #pragma unroll
    for (int p = 0; p < 32; p++) t2[p] = B_2[p];
    #pragma unroll
    for (int kp = 0; kp < 32; kp++) {
        float k0v, k1v;
        unpack2(t1[kp], k0v, k1v);
        u64 a0 = pack2(k0v, k0v);
        u64 a1 = pack2(k1v, k1v);
        int k0 = 2 * kp, k1 = 2 * kp + 1;
        #pragma unroll
        for (int p = 0; p < 32; p++) {
            FMA2(t2[p], a0, W_2[k0 * 32 + p], t2[p]);
            FMA2(t2[p], a1, W_2[k1 * 32 + p], t2[p]);
        }
    }
    #pragma unroll
    for (int p = 0; p < 32; p++) {
        float lo, hi;
        unpack2(t2[p], lo, hi);
        lo = fmaxf(lo, 0.1f * lo);
        hi = fmaxf(hi, 0.1f * hi);
        t2[p] = pack2(lo, hi);
    }

    u64 one2 = pack2(1.0f, 1.0f);
    #pragma unroll
    for (int p = 0; p < 16; p++) FMA2(rad2[p], one2, B_3[p], rad2[p]);
    #pragma unroll
    for (int kp = 0; kp < 32; kp++) {
        float k0v, k1v;
        unpack2(t2[kp], k0v, k1v);
        u64 a0 = pack2(k0v, k0v);
        u64 a1 = pack2(k1v, k1v);
        int k0 = 2 * kp, k1 = 2 * kp + 1;
        #pragma unroll
        for (int p = 0; p < 16; p++) {
            FMA2(rad2[p], a0, W_3[k0 * 16 + p], rad2[p]);
            FMA2(rad2[p], a1, W_3[k1 * 16 + p], rad2[p]);
        }
    }

    // store table row (128-bit stores)
    ulonglong2* dst = (ulonglong2*)(g_table + (size_t)t * 32);
    #pragma unroll
    for (int q = 0; q < 8; q++)
        dst[q] = make_ulonglong2(rad2[2 * q], rad2[2 * q + 1]);
}

// ---------------------------------------------------------------------------
// Moment accumulation for one edge on 2 packed channel pairs.
// ---------------------------------------------------------------------------
__device__ __forceinline__ void accum_pair(u64 acc2[10], u64 r, u64 X2, u64 Y2, u64 Z2) {
    u64 tx, ty, tz;
    MUL2(tx, r, X2); MUL2(ty, r, Y2); MUL2(tz, r, Z2);
    ADD2(acc2[0], acc2[0], r);
    ADD2(acc2[1], acc2[1], tx);
    ADD2(acc2[2], acc2[2], ty);
    ADD2(acc2[3], acc2[3], tz);
    FMA2(acc2[4], tx, X2, acc2[4]);
    FMA2(acc2[5], ty, Y2, acc2[5]);
    FMA2(acc2[6], tz, Z2, acc2[6]);
    FMA2(acc2[7], tx, Y2, acc2[7]);
    FMA2(acc2[8], tx, Z2, acc2[8]);
    FMA2(acc2[9], ty, Z2, acc2[9]);
}

// ---------------------------------------------------------------------------
// Fused per-node kernel. One warp per node; warp = 4 edge groups x 8 channel
// lanes; per step 4 edges in flight. Table rows loaded as ulonglong2 (the
// 16B IS the packed channel-pair layout: zero pack instructions).
// ---------------------------------------------------------------------------
__global__ __launch_bounds__(128)
void node_kernel(const float* __restrict__ w_v, const float* __restrict__ w_d,
                 float* __restrict__ out, int N)
{
    __shared__ float s_wv[32 * 32];
    __shared__ float s_wd[32 * 32];
    __shared__ float s_t[4][32][9];

    for (int i = threadIdx.x; i < 32 * 32; i += blockDim.x) {
        s_wv[i] = w_v[i];
        s_wd[i] = w_d[i];
    }
    __syncthreads();

    int warp = threadIdx.x >> 5;
    int lane = threadIdx.x & 31;
    int g = lane >> 3;      // edge group 0..3
    int l = lane & 7;       // channel quarter 0..7 (channels l*4 .. l*4+3)
    int n = blockIdx.x * 4 + warp;
    if (n >= N) return;

    const float4* srs = g_slot_rs + (size_t)n * SLOTS;
    const ulonglong2* tab = (const ulonglong2*)g_table;   // 8 per row
    int cnt = g_count[n];
    if (cnt > SLOTS) cnt = SLOTS;

    u64 acc2[2][10];
    #pragma unroll
    for (int p = 0; p < 2; p++)
        #pragma unroll
        for (int m = 0; m < 10; m++) acc2[p][m] = 0;

    for (int t0 = 0; t0 < cnt; t0 += 32) {
        float4 myrs = (t0 + lane < cnt) ? __ldg(&srs[t0 + lane])
                                        : make_float4(0.f, 0.f, 0.f, 0.f);
        int rem = cnt - t0; if (rem > 32) rem = 32;
        int full = rem >> 2;              // steps where all 4 groups are valid

        #pragma unroll 8
        for (int i = 0; i < full; i++) {
            int j = i * 4 + g;
            float u = __shfl_sync(0xffffffffu, myrs.w, j);
            float X = __shfl_sync(0xffffffffu, myrs.x, j);
            float Y = __shfl_sync(0xffffffffu, myrs.y, j);
            float Z = __shfl_sync(0xffffffffu, myrs.z, j);

            int idx = (int)u;
            float frac = u - (float)idx;
            const ulonglong2* rp = tab + idx * 8 + l;
            ulonglong2 v0 = __ldg(rp);      // .x = ch(4l,4l+1), .y = ch(4l+2,4l+3)
            ulonglong2 v1 = __ldg(rp + 8);

            u64 fr2 = pack2(frac, frac);
            float om = 1.0f - frac;
            u64 om2 = pack2(om, om);
            u64 X2 = pack2(X, X), Y2 = pack2(Y, Y), Z2 = pack2(Z, Z);

            u64 ta, tb, ra, rb;
            MUL2(ta, v1.x, fr2);  FMA2(ra, v0.x, om2, ta);
            MUL2(tb, v1.y, fr2);  FMA2(rb, v0.y, om2, tb);

            accum_pair(acc2[0], ra, X2, Y2, Z2);
            accum_pair(acc2[1], rb, X2, Y2, Z2);
        }

        if (rem & 3) {  // masked tail step
            int j = full * 4 + g;
            float u = __shfl_sync(0xffffffffu, myrs.w, j);
            float X = __shfl_sync(0xffffffffu, myrs.x, j);
            float Y = __shfl_sync(0xffffffffu, myrs.y, j);
            float Z = __shfl_sync(0xffffffffu, myrs.z, j);
            float wgt = (j < rem) ? 1.0f : 0.0f;

            int idx = (int)u;
            float frac = u - (float)idx;
            const ulonglong2* rp = tab + idx * 8 + l;
            ulonglong2 v0 = __ldg(rp);
            ulonglong2 v1 = __ldg(rp + 8);

            u64 fr2 = pack2(frac * wgt, frac * wgt);
            float om = (1.0f - frac) * wgt;
            u64 om2 = pack2(om, om);
            u64 X2 = pack2(X, X), Y2 = pack2(Y, Y), Z2 = pack2(Z, Z);

            u64 ta, tb, ra, rb;
            MUL2(ta, v1.x, fr2);  FMA2(ra, v0.x, om2, ta);
            MUL2(tb, v1.y, fr2);  FMA2(rb, v0.y, om2, tb);

            accum_pair(acc2[0], ra, X2, Y2, Z2);
            accum_pair(acc2[1], rb, X2, Y2, Z2);
        }
    }

    // unpack to scalars: acc[c][m] for channels c = 0..3 of this lane
    float acc[4][10];
    #pragma unroll
    for (int m = 0; m < 10; m++) {
        unpack2(acc2[0][m], acc[0][m], acc[1][m]);
        unpack2(acc2[1][m], acc[2][m], acc[3][m]);
    }

    // reduce across the 4 edge groups
    #pragma unroll
    for (int c = 0; c < 4; c++)
        #pragma unroll
        for (int m = 0; m < 10; m++) {
            acc[c][m] += __shfl_xor_sync(0xffffffffu, acc[c][m], 8);
            acc[c][m] += __shfl_xor_sync(0xffffffffu, acc[c][m], 16);
        }

    if (g == 0) {
        // A_a: channels l*4..l*4+3, contiguous float4 store
        float4 aav = make_float4(acc[0][0], acc[1][0], acc[2][0], acc[3][0]);
        *(float4*)(out + (size_t)n * 32 + l * 4) = aav;
        #pragma unroll
        for (int c = 0; c < 4; c++)
            #pragma unroll
            for (int m = 0; m < 9; m++)
                s_t[warp][l * 4 + c][m] = acc[c][m + 1];
    }
    __syncwarp();

    // lane = output channel
    float ov0 = 0.f, ov1 = 0.f, ov2 = 0.f;
    float od[6] = {0.f, 0.f, 0.f, 0.f, 0.f, 0.f};
    #pragma unroll
    for (int a = 0; a < 32; a++) {
        float wv = s_wv[a * 32 + lane];
        float wd = s_wd[a * 32 + lane];
        ov0 = fmaf(wv, s_t[warp][a][0], ov0);
        ov1 = fmaf(wv, s_t[warp][a][1], ov1);
        ov2 = fmaf(wv, s_t[warp][a][2], ov2);
        #pragma unroll
        for (int s = 0; s < 6; s++) od[s] = fmaf(wd, s_t[warp][a][3 + s], od[s]);
    }

    // out_v: [N][32][3] at offset N*32
    float* pv = out + (size_t)N * 32 + (size_t)n * 96 + lane * 3;
    pv[0] = ov0; pv[1] = ov1; pv[2] = ov2;

    // out_d: [N][32][3][3] at offset N*128 ; od = [XX,YY,ZZ,XY,XZ,YZ]
    float* pd = out + (size_t)N * 128 + (size_t)n * 288 + lane * 9;
    pd[0] = od[0]; pd[1] = od[3]; pd[2] = od[4];
    pd[3] = od[3]; pd[4] = od[1]; pd[5] = od[5];
    pd[6] = od[4]; pd[7] = od[5]; pd[8] = od[2];
}

// ---------------------------------------------------------------------------
// kernel_launch — 3 kernels: table(+zero) -> prep -> node
// ---------------------------------------------------------------------------
extern "C" void kernel_launch(void* const* d_in, const int* in_sizes, int n_in,
                              void* d_out, int out_size) {
    const float* r_ij     = (const float*)d_in[0];
    const float* w_rad    = (const float*)d_in[1];
    const float* b_rad    = (const float*)d_in[2];
    const float* w_direct = (const float*)d_in[3];
    const float* w1       = (const float*)d_in[4];
    const float* b1       = (const float*)d_in[5];
    const float* w2       = (const float*)d_in[6];
    const float* b2       = (const float*)d_in[7];
    const float* w3       = (const float*)d_in[8];
    const float* b3       = (const float*)d_in[9];
    const float* w_v      = (const float*)d_in[10];
    const float* w_d      = (const float*)d_in[11];
    const int*   e_src    = (const int*)  d_in[12];

    int E = in_sizes[0] / 3;
    int N = out_size / 416;

    float* out = (float*)d_out;

    // Table build + fused g_count zeroing (grid covers max(TABN, N) threads)
    int span = (TABN > N) ? TABN : N;
    table_kernel<<<(span + 127) / 128, 128>>>(
        w_rad, b_rad, w_direct, w1, b1, w2, b2, w3, b3, N);

    // Per-edge prep: payload (X,Y,Z,u) written straight into node slots
    prep_kernel<<<(E + 255) / 256, 256>>>(r_ij, e_src, E);

    // Fused gather + table interp + moments + contraction
    node_kernel<<<(N + 3) / 4, 128>>>(w_v, w_d, out, N);
}